// round 1
// baseline (speedup 1.0000x reference)
#include <cuda_runtime.h>
#include <math.h>

#define ZN 1024
#define NA 14
#define NAA 21
#define NV 4096          // 16^3
#define NTHREADS 256

// out layout: Cb [ZN*4*3] | div [ZN*4096] | frames [ZN*3*3]
#define DIV_OFF   (ZN * 12)
#define FR_OFF    (ZN * 12 + ZN * NV)

__global__ __launch_bounds__(NTHREADS) void pp_kernel(
    const float* __restrict__ C,
    const int*   __restrict__ L,
    const float* __restrict__ atom_mask,
    const float* __restrict__ charges,
    float* __restrict__ out)
{
    extern __shared__ float sf[];            // 3 * 4096 floats = 48 KB
    float* sfx = sf;
    float* sfy = sf + NV;
    float* sfz = sf + 2 * NV;
    __shared__ float sCx[NA], sCy[NA], sCz[NA];
    __shared__ float spc[NA];
    __shared__ float sfr[9];                 // frames[u][s] row-major
    __shared__ float sorig[3];

    const int n   = blockIdx.x;
    const int tid = threadIdx.x;
    const float* Cn = C + n * NA * 3;

    if (tid < NA) {
        sCx[tid] = Cn[tid * 3 + 0];
        sCy[tid] = Cn[tid * 3 + 1];
        sCz[tid] = Cn[tid * 3 + 2];
        int lbl = L[n];
        if (lbl == -1) lbl = NAA - 1;
        spc[tid] = charges[lbl * NA + tid] * atom_mask[n * NA + tid];
    }
    if (tid == 0) {
        float Nx = Cn[0], Ny = Cn[1], Nz = Cn[2];
        float Ax = Cn[3], Ay = Cn[4], Az = Cn[5];
        float Bx = Cn[6], By = Cn[7], Bz = Cn[8];   // "C" atom
        float b1x = Ax - Nx, b1y = Ay - Ny, b1z = Az - Nz;
        float b2x = Bx - Ax, b2y = By - Ay, b2z = Bz - Az;
        float b3x = b1y * b2z - b1z * b2y;
        float b3y = b1z * b2x - b1x * b2z;
        float b3z = b1x * b2y - b1y * b2x;
        float cbx = Ax - 0.58273431f * b2x + 0.56802827f * b1x - 0.54067466f * b3x;
        float cby = Ay - 0.58273431f * b2y + 0.56802827f * b1y - 0.54067466f * b3y;
        float cbz = Az - 0.58273431f * b2z + 0.56802827f * b1z - 0.54067466f * b3z;
        // y = cb - ca, normalized (clip 1e-6)
        float yx = cbx - Ax, yy = cby - Ay, yz = cbz - Az;
        float ynrm = fmaxf(sqrtf(yx * yx + yy * yy + yz * yz), 1e-6f);
        float yux = yx / ynrm, yuy = yy / ynrm, yuz = yz / ynrm;
        // x_raw = c - n ; x = x_raw - dot(x_raw, y_unit)  (SCALAR broadcast, per reference)
        float xrx = Bx - Nx, xry = By - Ny, xrz = Bz - Nz;
        float xp  = xrx * yux + xry * yuy + xrz * yuz;
        float xx = xrx - xp, xy = xry - xp, xz = xrz - xp;
        float xnrm = fmaxf(sqrtf(xx * xx + xy * xy + xz * xz), 1e-6f);
        float xux = xx / xnrm, xuy = xy / xnrm, xuz = xz / xnrm;
        // z = cross(x_unit, y_unit), normalized
        float zx = xuy * yuz - xuz * yuy;
        float zy = xuz * yux - xux * yuz;
        float zz = xux * yuy - xuy * yux;
        float znrm = fmaxf(sqrtf(zx * zx + zy * zy + zz * zz), 1e-6f);
        float zux = zx / znrm, zuy = zy / znrm, zuz = zz / znrm;

        sfr[0] = xux; sfr[1] = xuy; sfr[2] = xuz;
        sfr[3] = yux; sfr[4] = yuy; sfr[5] = yuz;
        sfr[6] = zux; sfr[7] = zuy; sfr[8] = zuz;
        sorig[0] = cbx; sorig[1] = cby; sorig[2] = cbz;

        // write Cb output: rows n, ca, c, cb
        float* cbo = out + n * 12;
        cbo[0] = Nx;  cbo[1] = Ny;  cbo[2] = Nz;
        cbo[3] = Ax;  cbo[4] = Ay;  cbo[5] = Az;
        cbo[6] = Bx;  cbo[7] = By;  cbo[8] = Bz;
        cbo[9] = cbx; cbo[10] = cby; cbo[11] = cbz;
        // write frames output
        float* fro = out + FR_OFF + n * 9;
        fro[0] = xux; fro[1] = xuy; fro[2] = xuz;
        fro[3] = yux; fro[4] = yuy; fro[5] = yuz;
        fro[6] = zux; fro[7] = zuy; fro[8] = zuz;
    }
    __syncthreads();

    const float fr0 = sfr[0], fr1 = sfr[1], fr2 = sfr[2];
    const float fr3 = sfr[3], fr4 = sfr[4], fr5 = sfr[5];
    const float fr6 = sfr[6], fr7 = sfr[7], fr8 = sfr[8];
    const float ox = sorig[0], oy = sorig[1], oz = sorig[2];

    // ---- field computation ----
    #pragma unroll 2
    for (int i = tid; i < NV; i += NTHREADS) {
        float vx = (float)(i >> 8)        - 8.0f;
        float vy = (float)((i >> 4) & 15) - 4.0f;
        float vz = (float)(i & 15)        - 8.0f;
        // p = origin + frames^T * v   (rot_s = sum_u v_u * fr[u][s])
        float px = ox + vx * fr0 + vy * fr3 + vz * fr6;
        float py = oy + vx * fr1 + vy * fr4 + vz * fr7;
        float pz = oz + vx * fr2 + vy * fr5 + vz * fr8;

        float fx = 0.f, fy = 0.f, fz = 0.f;
        #pragma unroll
        for (int a = 0; a < NA; a++) {
            float dx = px - sCx[a];
            float dy = py - sCy[a];
            float dz = pz - sCz[a];
            float d2 = fmaf(dx, dx, fmaf(dy, dy, dz * dz));
            float d2c = fmaxf(d2, 1e-24f);        // guard exact-zero; dv=0 there anyway
            float inv = rsqrtf(d2c);              // 1/d
            float inv3 = inv * inv * inv;         // 1/d^3
            float factor = (d2c >= 1.0f) ? inv3 : inv;  // d>=1: 1/d^3 ; d<1: 1/d
            float w = spc[a] * factor;
            fx = fmaf(w, dx, fx);
            fy = fmaf(w, dy, fy);
            fz = fmaf(w, dz, fz);
        }
        float fn2 = fmaf(fx, fx, fmaf(fy, fy, fz * fz));
        float rn = (fn2 > 0.f) ? rsqrtf(fn2) : 1.0f;
        sfx[i] = fx * rn;
        sfy[i] = fy * rn;
        sfz[i] = fz * rn;
    }
    __syncthreads();

    // ---- divergence (CELL_DIM r = 1) ----
    float* dvo = out + DIV_OFF + n * NV;
    #pragma unroll 2
    for (int i = tid; i < NV; i += NTHREADS) {
        int x = i >> 8;
        int y = (i >> 4) & 15;
        int z = i & 15;
        float ddx, ddy, ddz;
        if (x == 0)        ddx = sfx[i + 256] - sfx[i];
        else if (x == 15)  ddx = sfx[i] - sfx[i - 256];
        else               ddx = 0.5f * (sfx[i + 256] - sfx[i - 256]);
        if (y == 0)        ddy = sfy[i + 16] - sfy[i];
        else if (y == 15)  ddy = sfy[i] - sfy[i - 16];
        else               ddy = 0.5f * (sfy[i + 16] - sfy[i - 16]);
        if (z == 0)        ddz = sfz[i + 1] - sfz[i];
        else if (z == 15)  ddz = sfz[i] - sfz[i - 1];
        else               ddz = 0.5f * (sfz[i + 1] - sfz[i - 1]);
        dvo[i] = ddx + ddy + ddz;
    }
}

extern "C" void kernel_launch(void* const* d_in, const int* in_sizes, int n_in,
                              void* d_out, int out_size) {
    const float* C         = (const float*)d_in[0];
    const int*   L         = (const int*)d_in[1];
    const float* atom_mask = (const float*)d_in[2];
    const float* charges   = (const float*)d_in[3];
    float* out = (float*)d_out;

    // dynamic smem 48KB + a few hundred bytes static; opt in above default cap
    static bool attr_set = false;
    if (!attr_set) {
        cudaFuncSetAttribute(pp_kernel, cudaFuncAttributeMaxDynamicSharedMemorySize, 64 * 1024);
        attr_set = true;
    }
    pp_kernel<<<ZN, NTHREADS, 3 * NV * sizeof(float)>>>(C, L, atom_mask, charges, out);
}

// round 2
// speedup vs baseline: 1.7236x; 1.7236x over previous
#include <cuda_runtime.h>
#include <math.h>

#define ZN 1024
#define NA 14
#define NAA 21
#define NV 4096          // 16^3
#define NTHREADS 256

// out layout: Cb [ZN*4*3] | div [ZN*4096] | frames [ZN*3*3]
#define DIV_OFF   (ZN * 12)
#define FR_OFF    (ZN * 12 + ZN * NV)

typedef unsigned long long u64;

__device__ __forceinline__ u64 pk2(float lo, float hi) {
    u64 r; asm("mov.b64 %0,{%1,%2};" : "=l"(r) : "f"(lo), "f"(hi)); return r;
}
__device__ __forceinline__ void upk2(u64 v, float &lo, float &hi) {
    asm("mov.b64 {%0,%1},%2;" : "=f"(lo), "=f"(hi) : "l"(v));
}
__device__ __forceinline__ u64 add2(u64 a, u64 b) {
    u64 r; asm("add.rn.f32x2 %0,%1,%2;" : "=l"(r) : "l"(a), "l"(b)); return r;
}
__device__ __forceinline__ u64 mul2(u64 a, u64 b) {
    u64 r; asm("mul.rn.f32x2 %0,%1,%2;" : "=l"(r) : "l"(a), "l"(b)); return r;
}
__device__ __forceinline__ u64 fma2_(u64 a, u64 b, u64 c) {
    u64 r; asm("fma.rn.f32x2 %0,%1,%2,%3;" : "=l"(r) : "l"(a), "l"(b), "l"(c)); return r;
}

__global__ __launch_bounds__(NTHREADS, 2) void pp_kernel(
    const float* __restrict__ C,
    const int*   __restrict__ L,
    const float* __restrict__ atom_mask,
    const float* __restrict__ charges,
    float* __restrict__ out)
{
    extern __shared__ float sf[];            // 3 * 4096 floats = 48 KB
    float* sfx = sf;
    float* sfy = sf + NV;
    float* sfz = sf + 2 * NV;
    __shared__ float sfr[9];                 // frames[u][s] row-major
    __shared__ float sorig[3];

    const int n   = blockIdx.x;
    const int tid = threadIdx.x;
    const float* Cn = C + n * NA * 3;

    if (tid == 0) {
        float Nx = Cn[0], Ny = Cn[1], Nz = Cn[2];
        float Ax = Cn[3], Ay = Cn[4], Az = Cn[5];
        float Bx = Cn[6], By = Cn[7], Bz = Cn[8];   // "C" atom
        float b1x = Ax - Nx, b1y = Ay - Ny, b1z = Az - Nz;
        float b2x = Bx - Ax, b2y = By - Ay, b2z = Bz - Az;
        float b3x = b1y * b2z - b1z * b2y;
        float b3y = b1z * b2x - b1x * b2z;
        float b3z = b1x * b2y - b1y * b2x;
        float cbx = Ax - 0.58273431f * b2x + 0.56802827f * b1x - 0.54067466f * b3x;
        float cby = Ay - 0.58273431f * b2y + 0.56802827f * b1y - 0.54067466f * b3y;
        float cbz = Az - 0.58273431f * b2z + 0.56802827f * b1z - 0.54067466f * b3z;
        // y = cb - ca, normalized (clip 1e-6)
        float yx = cbx - Ax, yy = cby - Ay, yz = cbz - Az;
        float ynrm = fmaxf(sqrtf(yx * yx + yy * yy + yz * yz), 1e-6f);
        float yux = yx / ynrm, yuy = yy / ynrm, yuz = yz / ynrm;
        // x_raw = c - n ; x = x_raw - dot(x_raw, y_unit) (scalar broadcast, per reference)
        float xrx = Bx - Nx, xry = By - Ny, xrz = Bz - Nz;
        float xp  = xrx * yux + xry * yuy + xrz * yuz;
        float xx = xrx - xp, xy = xry - xp, xz = xrz - xp;
        float xnrm = fmaxf(sqrtf(xx * xx + xy * xy + xz * xz), 1e-6f);
        float xux = xx / xnrm, xuy = xy / xnrm, xuz = xz / xnrm;
        // z = cross(x_unit, y_unit), normalized
        float zx = xuy * yuz - xuz * yuy;
        float zy = xuz * yux - xux * yuz;
        float zz = xux * yuy - xuy * yux;
        float znrm = fmaxf(sqrtf(zx * zx + zy * zy + zz * zz), 1e-6f);
        float zux = zx / znrm, zuy = zy / znrm, zuz = zz / znrm;

        sfr[0] = xux; sfr[1] = xuy; sfr[2] = xuz;
        sfr[3] = yux; sfr[4] = yuy; sfr[5] = yuz;
        sfr[6] = zux; sfr[7] = zuy; sfr[8] = zuz;
        sorig[0] = cbx; sorig[1] = cby; sorig[2] = cbz;

        float* cbo = out + n * 12;
        cbo[0] = Nx;  cbo[1] = Ny;  cbo[2] = Nz;
        cbo[3] = Ax;  cbo[4] = Ay;  cbo[5] = Az;
        cbo[6] = Bx;  cbo[7] = By;  cbo[8] = Bz;
        cbo[9] = cbx; cbo[10] = cby; cbo[11] = cbz;
        float* fro = out + FR_OFF + n * 9;
        fro[0] = xux; fro[1] = xuy; fro[2] = xuz;
        fro[3] = yux; fro[4] = yuy; fro[5] = yuz;
        fro[6] = zux; fro[7] = zuy; fro[8] = zuz;
    }

    // ---- per-thread atom constants: 7 packed pairs (2 atoms per f32x2 lane) ----
    int lbl = L[n];
    if (lbl == -1) lbl = NAA - 1;
    const float* ch = charges + lbl * NA;
    const float* am = atom_mask + n * NA;

    u64 nCx[7], nCy[7], nCz[7], pcp[7];
    #pragma unroll
    for (int j = 0; j < 7; j++) {
        nCx[j] = pk2(-Cn[6 * j + 0], -Cn[6 * j + 3]);
        nCy[j] = pk2(-Cn[6 * j + 1], -Cn[6 * j + 4]);
        nCz[j] = pk2(-Cn[6 * j + 2], -Cn[6 * j + 5]);
        pcp[j] = pk2(ch[2 * j] * am[2 * j], ch[2 * j + 1] * am[2 * j + 1]);
    }

    __syncthreads();

    const float fr0 = sfr[0], fr1 = sfr[1], fr2 = sfr[2];
    const float ox = sorig[0], oy = sorig[1], oz = sorig[2];

    // thread owns the x-line: voxel index i = tid + 256*k, k = x coordinate
    const float vy = (float)(tid >> 4) - 4.0f;
    const float vz = (float)(tid & 15) - 8.0f;
    // start position at x = 0 (vx = -8), packed (both lanes identical)
    float px0 = ox + (-8.0f) * fr0 + vy * sfr[3] + vz * sfr[6];
    float py0 = oy + (-8.0f) * fr1 + vy * sfr[4] + vz * sfr[7];
    float pz0 = oz + (-8.0f) * fr2 + vy * sfr[5] + vz * sfr[8];
    u64 pxp = pk2(px0, px0);
    u64 pyp = pk2(py0, py0);
    u64 pzp = pk2(pz0, pz0);
    const u64 sxp = pk2(fr0, fr0);
    const u64 syp = pk2(fr1, fr1);
    const u64 szp = pk2(fr2, fr2);

    #pragma unroll 1
    for (int k = 0; k < 16; k++) {
        u64 fxp = 0ULL, fyp = 0ULL, fzp = 0ULL;   // (0.0f, 0.0f)
        #pragma unroll
        for (int j = 0; j < 7; j++) {
            u64 dx = add2(pxp, nCx[j]);
            u64 dy = add2(pyp, nCy[j]);
            u64 dz = add2(pzp, nCz[j]);
            u64 d2 = fma2_(dx, dx, fma2_(dy, dy, mul2(dz, dz)));
            float a, b;
            upk2(d2, a, b);
            // factor = (1/d^3) * min(d^2, 1):  d>=1 -> 1/d^3 ; d<1 -> 1/d
            float dca = fmaxf(a, 1e-30f);
            float ia  = rsqrtf(dca);
            float sa  = fminf(dca, 1.0f);
            float fa  = ia * ia * ia * sa;
            float dcb = fmaxf(b, 1e-30f);
            float ib  = rsqrtf(dcb);
            float sb  = fminf(dcb, 1.0f);
            float fb  = ib * ib * ib * sb;
            u64 wp = mul2(pk2(fa, fb), pcp[j]);
            fxp = fma2_(wp, dx, fxp);
            fyp = fma2_(wp, dy, fyp);
            fzp = fma2_(wp, dz, fzp);
        }
        // horizontal sum of the two atom lanes
        float fxa, fxb, fya, fyb, fza, fzb;
        upk2(fxp, fxa, fxb);
        upk2(fyp, fya, fyb);
        upk2(fzp, fza, fzb);
        float fx = fxa + fxb, fy = fya + fyb, fz = fza + fzb;
        float fn2 = fmaf(fx, fx, fmaf(fy, fy, fz * fz));
        float rn = (fn2 > 0.0f) ? rsqrtf(fn2) : 1.0f;
        int i = tid + (k << 8);
        sfx[i] = fx * rn;
        sfy[i] = fy * rn;
        sfz[i] = fz * rn;
        pxp = add2(pxp, sxp);
        pyp = add2(pyp, syp);
        pzp = add2(pzp, szp);
    }
    __syncthreads();

    // ---- divergence (CELL_DIM r = 1) ----
    float* dvo = out + DIV_OFF + n * NV;
    #pragma unroll 1
    for (int k = 0; k < 16; k++) {
        int i = tid + (k << 8);
        int x = k;
        int y = tid >> 4;
        int z = tid & 15;
        float ddx, ddy, ddz;
        if (x == 0)        ddx = sfx[i + 256] - sfx[i];
        else if (x == 15)  ddx = sfx[i] - sfx[i - 256];
        else               ddx = 0.5f * (sfx[i + 256] - sfx[i - 256]);
        if (y == 0)        ddy = sfy[i + 16] - sfy[i];
        else if (y == 15)  ddy = sfy[i] - sfy[i - 16];
        else               ddy = 0.5f * (sfy[i + 16] - sfy[i - 16]);
        if (z == 0)        ddz = sfz[i + 1] - sfz[i];
        else if (z == 15)  ddz = sfz[i] - sfz[i - 1];
        else               ddz = 0.5f * (sfz[i + 1] - sfz[i - 1]);
        dvo[i] = ddx + ddy + ddz;
    }
}

extern "C" void kernel_launch(void* const* d_in, const int* in_sizes, int n_in,
                              void* d_out, int out_size) {
    const float* C         = (const float*)d_in[0];
    const int*   L         = (const int*)d_in[1];
    const float* atom_mask = (const float*)d_in[2];
    const float* charges   = (const float*)d_in[3];
    float* out = (float*)d_out;

    static bool attr_set = false;
    if (!attr_set) {
        cudaFuncSetAttribute(pp_kernel, cudaFuncAttributeMaxDynamicSharedMemorySize, 64 * 1024);
        attr_set = true;
    }
    pp_kernel<<<ZN, NTHREADS, 3 * NV * sizeof(float)>>>(C, L, atom_mask, charges, out);
}

// round 3
// speedup vs baseline: 1.7972x; 1.0427x over previous
#include <cuda_runtime.h>
#include <math.h>

#define ZN 1024
#define NA 14
#define NAA 21
#define NV 4096          // 16^3
#define NTHREADS 256

// out layout: Cb [ZN*4*3] | div [ZN*4096] | frames [ZN*3*3]
#define DIV_OFF   (ZN * 12)
#define FR_OFF    (ZN * 12 + ZN * NV)

typedef unsigned long long u64;

__device__ __forceinline__ u64 pk2(float lo, float hi) {
    u64 r; asm("mov.b64 %0,{%1,%2};" : "=l"(r) : "f"(lo), "f"(hi)); return r;
}
__device__ __forceinline__ void upk2(u64 v, float &lo, float &hi) {
    asm("mov.b64 {%0,%1},%2;" : "=f"(lo), "=f"(hi) : "l"(v));
}
__device__ __forceinline__ u64 add2(u64 a, u64 b) {
    u64 r; asm("add.rn.f32x2 %0,%1,%2;" : "=l"(r) : "l"(a), "l"(b)); return r;
}
__device__ __forceinline__ u64 mul2(u64 a, u64 b) {
    u64 r; asm("mul.rn.f32x2 %0,%1,%2;" : "=l"(r) : "l"(a), "l"(b)); return r;
}
__device__ __forceinline__ u64 fma2_(u64 a, u64 b, u64 c) {
    u64 r; asm("fma.rn.f32x2 %0,%1,%2,%3;" : "=l"(r) : "l"(a), "l"(b), "l"(c)); return r;
}
__device__ __forceinline__ float rsqrt_fast(float x) {
    float r; asm("rsqrt.approx.f32 %0,%1;" : "=f"(r) : "f"(x)); return r;
}

__global__ __launch_bounds__(NTHREADS, 2) void pp_kernel(
    const float* __restrict__ C,
    const int*   __restrict__ L,
    const float* __restrict__ atom_mask,
    const float* __restrict__ charges,
    float* __restrict__ out)
{
    extern __shared__ float sf[];            // 3 * 4096 floats = 48 KB
    float* sfx = sf;
    float* sfy = sf + NV;
    float* sfz = sf + 2 * NV;
    __shared__ float sfr[9];                 // frames[u][s] row-major
    __shared__ float sorig[3];

    const int n   = blockIdx.x;
    const int tid = threadIdx.x;
    const float* Cn = C + n * NA * 3;

    if (tid == 0) {
        float Nx = Cn[0], Ny = Cn[1], Nz = Cn[2];
        float Ax = Cn[3], Ay = Cn[4], Az = Cn[5];
        float Bx = Cn[6], By = Cn[7], Bz = Cn[8];   // "C" atom
        float b1x = Ax - Nx, b1y = Ay - Ny, b1z = Az - Nz;
        float b2x = Bx - Ax, b2y = By - Ay, b2z = Bz - Az;
        float b3x = b1y * b2z - b1z * b2y;
        float b3y = b1z * b2x - b1x * b2z;
        float b3z = b1x * b2y - b1y * b2x;
        float cbx = Ax - 0.58273431f * b2x + 0.56802827f * b1x - 0.54067466f * b3x;
        float cby = Ay - 0.58273431f * b2y + 0.56802827f * b1y - 0.54067466f * b3y;
        float cbz = Az - 0.58273431f * b2z + 0.56802827f * b1z - 0.54067466f * b3z;
        // y = cb - ca, normalized (clip 1e-6)
        float yx = cbx - Ax, yy = cby - Ay, yz = cbz - Az;
        float ynrm = fmaxf(sqrtf(yx * yx + yy * yy + yz * yz), 1e-6f);
        float yux = yx / ynrm, yuy = yy / ynrm, yuz = yz / ynrm;
        // x_raw = c - n ; x = x_raw - dot(x_raw, y_unit) (scalar broadcast, per reference)
        float xrx = Bx - Nx, xry = By - Ny, xrz = Bz - Nz;
        float xp  = xrx * yux + xry * yuy + xrz * yuz;
        float xx = xrx - xp, xy = xry - xp, xz = xrz - xp;
        float xnrm = fmaxf(sqrtf(xx * xx + xy * xy + xz * xz), 1e-6f);
        float xux = xx / xnrm, xuy = xy / xnrm, xuz = xz / xnrm;
        // z = cross(x_unit, y_unit), normalized
        float zx = xuy * yuz - xuz * yuy;
        float zy = xuz * yux - xux * yuz;
        float zz = xux * yuy - xuy * yux;
        float znrm = fmaxf(sqrtf(zx * zx + zy * zy + zz * zz), 1e-6f);
        float zux = zx / znrm, zuy = zy / znrm, zuz = zz / znrm;

        sfr[0] = xux; sfr[1] = xuy; sfr[2] = xuz;
        sfr[3] = yux; sfr[4] = yuy; sfr[5] = yuz;
        sfr[6] = zux; sfr[7] = zuy; sfr[8] = zuz;
        sorig[0] = cbx; sorig[1] = cby; sorig[2] = cbz;

        float* cbo = out + n * 12;
        cbo[0] = Nx;  cbo[1] = Ny;  cbo[2] = Nz;
        cbo[3] = Ax;  cbo[4] = Ay;  cbo[5] = Az;
        cbo[6] = Bx;  cbo[7] = By;  cbo[8] = Bz;
        cbo[9] = cbx; cbo[10] = cby; cbo[11] = cbz;
        float* fro = out + FR_OFF + n * 9;
        fro[0] = xux; fro[1] = xuy; fro[2] = xuz;
        fro[3] = yux; fro[4] = yuy; fro[5] = yuz;
        fro[6] = zux; fro[7] = zuy; fro[8] = zuz;
    }

    // ---- per-thread atom constants: 7 packed pairs (2 atoms per f32x2 lane) ----
    int lbl = L[n];
    if (lbl == -1) lbl = NAA - 1;
    const float* ch = charges + lbl * NA;
    const float* am = atom_mask + n * NA;

    u64 nCx[7], nCy[7], nCz[7], pcp[7];
    #pragma unroll
    for (int j = 0; j < 7; j++) {
        nCx[j] = pk2(-Cn[6 * j + 0], -Cn[6 * j + 3]);
        nCy[j] = pk2(-Cn[6 * j + 1], -Cn[6 * j + 4]);
        nCz[j] = pk2(-Cn[6 * j + 2], -Cn[6 * j + 5]);
        pcp[j] = pk2(ch[2 * j] * am[2 * j], ch[2 * j + 1] * am[2 * j + 1]);
    }

    __syncthreads();

    const float fr0 = sfr[0], fr1 = sfr[1], fr2 = sfr[2];
    const float ox = sorig[0], oy = sorig[1], oz = sorig[2];

    // thread owns the x-line: voxel index i = tid + 256*k, k = x coordinate
    const float vy = (float)(tid >> 4) - 4.0f;
    const float vz = (float)(tid & 15) - 8.0f;
    float px0 = ox + (-8.0f) * fr0 + vy * sfr[3] + vz * sfr[6];
    float py0 = oy + (-8.0f) * fr1 + vy * sfr[4] + vz * sfr[7];
    float pz0 = oz + (-8.0f) * fr2 + vy * sfr[5] + vz * sfr[8];
    u64 pxp = pk2(px0, px0);
    u64 pyp = pk2(py0, py0);
    u64 pzp = pk2(pz0, pz0);
    const u64 sxp = pk2(fr0, fr0);
    const u64 syp = pk2(fr1, fr1);
    const u64 szp = pk2(fr2, fr2);
    const u64 eps2 = pk2(1e-30f, 1e-30f);   // zero-distance guard folded into d2

    #pragma unroll 1
    for (int k = 0; k < 16; k++) {
        u64 fxp = 0ULL, fyp = 0ULL, fzp = 0ULL;
        #pragma unroll
        for (int j = 0; j < 7; j++) {
            u64 dx = add2(pxp, nCx[j]);
            u64 dy = add2(pyp, nCy[j]);
            u64 dz = add2(pzp, nCz[j]);
            u64 d2 = fma2_(dx, dx, fma2_(dy, dy, fma2_(dz, dz, eps2)));
            float a, b;
            upk2(d2, a, b);
            // factor = (1/d^3) * min(d^2,1): d>=1 -> 1/d^3 ; d<1 -> 1/d
            float ia = rsqrt_fast(a);
            float ib = rsqrt_fast(b);
            float sa = fminf(a, 1.0f);
            float sb = fminf(b, 1.0f);
            u64 iap = pk2(ia, ib);
            u64 sap = pk2(sa, sb);
            u64 i2p = mul2(iap, iap);
            u64 wp  = mul2(mul2(i2p, mul2(iap, sap)), pcp[j]);
            fxp = fma2_(wp, dx, fxp);
            fyp = fma2_(wp, dy, fyp);
            fzp = fma2_(wp, dz, fzp);
        }
        // horizontal sum of the two atom lanes
        float fxa, fxb, fya, fyb, fza, fzb;
        upk2(fxp, fxa, fxb);
        upk2(fyp, fya, fyb);
        upk2(fzp, fza, fzb);
        float fx = fxa + fxb, fy = fya + fyb, fz = fza + fzb;
        float fn2 = fmaxf(fmaf(fx, fx, fmaf(fy, fy, fz * fz)), 1e-38f);
        float rn = rsqrt_fast(fn2);   // fn2==0 -> fields are 0 anyway; 0*huge = 0
        int i = tid + (k << 8);
        sfx[i] = fx * rn;
        sfy[i] = fy * rn;
        sfz[i] = fz * rn;
        pxp = add2(pxp, sxp);
        pyp = add2(pyp, syp);
        pzp = add2(pzp, szp);
    }
    __syncthreads();

    // ---- divergence (CELL_DIM r = 1) ----
    float* dvo = out + DIV_OFF + n * NV;
    #pragma unroll 1
    for (int k = 0; k < 16; k++) {
        int i = tid + (k << 8);
        int x = k;
        int y = tid >> 4;
        int z = tid & 15;
        float ddx, ddy, ddz;
        if (x == 0)        ddx = sfx[i + 256] - sfx[i];
        else if (x == 15)  ddx = sfx[i] - sfx[i - 256];
        else               ddx = 0.5f * (sfx[i + 256] - sfx[i - 256]);
        if (y == 0)        ddy = sfy[i + 16] - sfy[i];
        else if (y == 15)  ddy = sfy[i] - sfy[i - 16];
        else               ddy = 0.5f * (sfy[i + 16] - sfy[i - 16]);
        if (z == 0)        ddz = sfz[i + 1] - sfz[i];
        else if (z == 15)  ddz = sfz[i] - sfz[i - 1];
        else               ddz = 0.5f * (sfz[i + 1] - sfz[i - 1]);
        dvo[i] = ddx + ddy + ddz;
    }
}

extern "C" void kernel_launch(void* const* d_in, const int* in_sizes, int n_in,
                              void* d_out, int out_size) {
    const float* C         = (const float*)d_in[0];
    const int*   L         = (const int*)d_in[1];
    const float* atom_mask = (const float*)d_in[2];
    const float* charges   = (const float*)d_in[3];
    float* out = (float*)d_out;

    static bool attr_set = false;
    if (!attr_set) {
        cudaFuncSetAttribute(pp_kernel, cudaFuncAttributeMaxDynamicSharedMemorySize, 64 * 1024);
        attr_set = true;
    }
    pp_kernel<<<ZN, NTHREADS, 3 * NV * sizeof(float)>>>(C, L, atom_mask, charges, out);
}